// round 16
// baseline (speedup 1.0000x reference)
#include <cuda_runtime.h>
#include <cuda_bf16.h>
#include <math.h>
#include <stdint.h>

// ---- problem constants ----
#define NB    4
#define LL    512
#define NNODE 2048
#define D0V   640
#define PV    128
#define CV    32
#define HV    4
#define NLV   3
#define RADIN 130
#define HIDV  64
#define R4C   128
#define EMAX  262144

typedef unsigned long long ull;

// ---- device scratch ----
__device__ float g_h0  [NNODE*CV];
__device__ float g_h1x [NNODE*CV];
__device__ float g_h1y [NNODE*CV];
__device__ float g_h1z [NNODE*CV];
__device__ float g_q   [NNODE*CV];
__device__ float g_a00 [2][NNODE*CV];
__device__ float g_a10 [2][NNODE*CV];
__device__ float g_g01x[2][NNODE*CV];
__device__ float g_g01y[2][NNODE*CV];
__device__ float g_g01z[2][NNODE*CV];
__device__ float g_g11x[2][NNODE*CV];
__device__ float g_g11y[2][NNODE*CV];
__device__ float g_g11z[2][NNODE*CV];
__device__ unsigned char g_a1h[(size_t)(EMAX/16)*4096];
__device__ unsigned char g_a1l[(size_t)(EMAX/16)*4096];
__device__ uint4 g_B1t[NLV*2048];
__device__ uint4 g_B2t[NLV*2048];
__device__ float g_rad [(size_t)NLV*EMAX*R4C];
__device__ float2 g_bpr[EMAX];
__device__ float g_rhat[(size_t)EMAX*3];
__device__ float g_logit[(size_t)EMAX*HV];
__device__ int   g_deg   [NNODE];
__device__ int   g_rowptr[NNODE+1];
__device__ int   g_cursor[NNODE];
__device__ int   g_ceidx [EMAX];

// ---- helpers ----
__device__ __forceinline__ float warpsum(float v){
    #pragma unroll
    for (int o = 16; o; o >>= 1) v += __shfl_xor_sync(0xffffffffu, v, o);
    return v;
}
__device__ __forceinline__ uint32_t bf16pack(float a, float b){
    __nv_bfloat162 t = __floats2bfloat162_rn(a, b);
    return *(uint32_t*)&t;
}
__device__ __forceinline__ float bf16hi(float a){
    return __bfloat162float(__float2bfloat16_rn(a));
}

#define MMA_BF16(c, ax, ay, az, aw, b0, b1) \
    asm volatile("mma.sync.aligned.m16n8k16.row.col.f32.bf16.bf16.f32 " \
        "{%0,%1,%2,%3}, {%4,%5,%6,%7}, {%8,%9}, {%0,%1,%2,%3};" \
        : "+f"((c)[0]), "+f"((c)[1]), "+f"((c)[2]), "+f"((c)[3]) \
        : "r"(ax), "r"(ay), "r"(az), "r"(aw), "r"(b0), "r"(b1))

// ---- B fragment tables (all layers) ----
__global__ void k_btab(const float* __restrict__ Wr1all,
                       const float* __restrict__ Wr2all){
    int gidx = blockIdx.x*256 + threadIdx.x;
    int gstride = gridDim.x*256;
    for (int idx = gidx; idx < NLV*2048; idx += gstride){
        int l = idx >> 11, t = idx & 2047;
        int lf = t & 31, nt = (t >> 5) & 7, kk = t >> 8;
        int n  = nt*8 + (lf >> 2);
        int k0 = kk*16 + (lf & 3)*2;
        const float* W = Wr1all + l*RADIN*HIDV;
        float v0 = W[k0*64 + n],     v1 = W[(k0+1)*64 + n];
        float v2 = W[(k0+8)*64 + n], v3 = W[(k0+9)*64 + n];
        uint4 val;
        val.x = bf16pack(v0, v1);
        val.y = bf16pack(v2, v3);
        val.z = bf16pack(v0 - bf16hi(v0), v1 - bf16hi(v1));
        val.w = bf16pack(v2 - bf16hi(v2), v3 - bf16hi(v3));
        g_B1t[idx] = val;
    }
    for (int idx = gidx; idx < NLV*2048; idx += gstride){
        int l = idx >> 11, t = idx & 2047;
        int lf = t & 31, nt = (t >> 5) & 15, kk = t >> 9;
        int n  = nt*8 + (lf >> 2);
        int k0 = kk*16 + (lf & 3)*2;
        const float* W = Wr2all + l*HIDV*R4C;
        float v0 = W[k0*128 + n],     v1 = W[(k0+1)*128 + n];
        float v2 = W[(k0+8)*128 + n], v3 = W[(k0+9)*128 + n];
        uint4 val;
        val.x = bf16pack(v0, v1);
        val.y = bf16pack(v2, v3);
        val.z = bf16pack(v0 - bf16hi(v0), v1 - bf16hi(v1));
        val.w = bf16pack(v2 - bf16hi(v2), v3 - bf16hi(v3));
        g_B2t[idx] = val;
    }
}

// ---- K0: h0 = seq @ Win0 ; h1 = x * Win1 ----
__global__ void k_init_nodes(const float* __restrict__ seq,
                             const float* __restrict__ coords,
                             const float* __restrict__ Win0,
                             const float* __restrict__ Win1){
    extern __shared__ float sm[];
    float* sW   = sm;
    float* sSeq = sm + 20480;
    int tid = threadIdx.x;
    for (int i = tid; i < D0V*CV; i += 512) sW[i] = Win0[i];
    int n0 = blockIdx.x * 16;
    for (int i = tid; i < 16*D0V; i += 512) sSeq[i] = seq[(size_t)n0*D0V + i];
    __syncthreads();
    int w = tid >> 5, lane = tid & 31;
    int n = n0 + w;
    const float* srow = sSeq + w*D0V;
    float acc = 0.f;
    #pragma unroll 4
    for (int i = 0; i < D0V; i++) acc += srow[i]*sW[i*CV + lane];
    g_h0[n*CV + lane] = acc;
    float wv = Win1[lane];
    g_h1x[n*CV+lane] = coords[n*3+0]*wv;
    g_h1y[n*CV+lane] = coords[n*3+1]*wv;
    g_h1z[n*CV+lane] = coords[n*3+2]*wv;
}

// ---- K1: geometry + fragment-major bf16 hi/lo A tiles + (bppm,r) + deg ----
__global__ void k_edge_setup(const float* __restrict__ coords,
                             const float* __restrict__ pair,
                             const float* __restrict__ bppm,
                             const int* __restrict__ src,
                             const int* __restrict__ dst, int E){
    int w = threadIdx.x >> 5, lane = threadIdx.x & 31;
    for (int e = blockIdx.x*8 + w; e < E; e += gridDim.x*8){
        int s = src[e], d = dst[e];
        int di = d & (LL-1);
        if (lane == 0){
            atomicAdd(&g_deg[d], 1);
            float rx = coords[d*3+0]-coords[s*3+0];
            float ry = coords[d*3+1]-coords[s*3+1];
            float rz = coords[d*3+2]-coords[s*3+2];
            float r  = sqrtf(rx*rx + ry*ry + rz*rz + 1e-12f);
            float inv = 1.f/(r + 1e-8f);
            g_rhat[(size_t)e*3+0] = rx*inv;
            g_rhat[(size_t)e*3+1] = ry*inv;
            g_rhat[(size_t)e*3+2] = rz*inv;
            g_bpr[e] = make_float2(bppm[(size_t)s*LL + di], r);
        }
        float4 pv = ((const float4*)(pair + ((size_t)s*LL + di)*PV))[lane];
        float h0 = bf16hi(pv.x), h1 = bf16hi(pv.y), h2 = bf16hi(pv.z), h3 = bf16hi(pv.w);
        uint32_t w0h = bf16pack(pv.x, pv.y);
        uint32_t w1h = bf16pack(pv.z, pv.w);
        uint32_t w0l = bf16pack(pv.x - h0, pv.y - h1);
        uint32_t w1l = bf16pack(pv.z - h2, pv.w - h3);
        int mc = e >> 4, r = e & 15;
        int kk = lane >> 2, m4 = lane & 3;
        int regb = (m4 < 2) ? 0 : 2;
        int reg  = regb + ((r < 8) ? 0 : 1);
        int lt01 = (r & 7)*4 + (m4 & 1)*2;
        int lt23 = lt01 + 1;
        size_t base = (size_t)mc*4096 + (size_t)kk*512;
        *(uint32_t*)(g_a1h + base + lt01*16 + reg*4) = w0h;
        *(uint32_t*)(g_a1h + base + lt23*16 + reg*4) = w1h;
        *(uint32_t*)(g_a1l + base + lt01*16 + reg*4) = w0l;
        *(uint32_t*)(g_a1l + base + lt23*16 + reg*4) = w1l;
    }
}

// ---- K2: per-node precompute (layer 0) -> writes buffer 0 ----
__global__ void k_node_pre(const float* __restrict__ Wq,
                           const float* __restrict__ Wm00,
                           const float* __restrict__ Wm10,
                           const float* __restrict__ Wm01,
                           const float* __restrict__ Wm11){
    __shared__ float sWq[1024], s00[1024], s10w[1024], s01[1024], s11[1024];
    int tid = threadIdx.x;
    for (int i = tid; i < 1024; i += 256){
        sWq[i] = Wq[i]; s00[i] = Wm00[i]; s10w[i] = Wm10[i];
        s01[i] = Wm01[i]; s11[i] = Wm11[i];
    }
    __syncthreads();
    int w = tid >> 5, lane = tid & 31;
    for (int n = blockIdx.x*8 + w; n < NNODE; n += gridDim.x*8){
        float h  = g_h0 [n*CV + lane];
        float hx = g_h1x[n*CV + lane];
        float hy = g_h1y[n*CV + lane];
        float hz = g_h1z[n*CV + lane];
        float q=0, a00=0, a10=0;
        float g01x=0,g01y=0,g01z=0,g11x=0,g11y=0,g11z=0;
        #pragma unroll 8
        for (int c = 0; c < CV; c++){
            float hc  = __shfl_sync(0xffffffffu, h,  c);
            float hcx = __shfl_sync(0xffffffffu, hx, c);
            float hcy = __shfl_sync(0xffffffffu, hy, c);
            float hcz = __shfl_sync(0xffffffffu, hz, c);
            q   += hc*sWq [c*CV+lane];
            a00 += hc*s00 [c*CV+lane];
            a10 += hc*s10w[c*CV+lane];
            float w01 = s01[c*CV+lane], w11 = s11[c*CV+lane];
            g01x += hcx*w01; g01y += hcy*w01; g01z += hcz*w01;
            g11x += hcx*w11; g11y += hcy*w11; g11z += hcz*w11;
        }
        g_q  [n*CV+lane] = q;
        g_a00[0][n*CV+lane] = a00;
        g_a10[0][n*CV+lane] = a10;
        g_g01x[0][n*CV+lane]=g01x; g_g01y[0][n*CV+lane]=g01y; g_g01z[0][n*CV+lane]=g01z;
        g_g11x[0][n*CV+lane]=g11x; g_g11y[0][n*CV+lane]=g11y; g_g11z[0][n*CV+lane]=g11z;
    }
}

// ---- CSR scan (+ deg reset) + fill ----
__global__ void k_scan(int E){
    __shared__ int s[NNODE];
    int t = threadIdx.x;
    s[t] = g_deg[t]; s[t+1024] = g_deg[t+1024];
    g_deg[t] = 0; g_deg[t+1024] = 0;
    __syncthreads();
    for (int off = 1; off < NNODE; off <<= 1){
        int v0 = (t >= off) ? s[t-off] : 0;
        int i1 = t + 1024;
        int v1 = (i1 >= off) ? s[i1-off] : 0;
        __syncthreads();
        s[t] += v0; s[i1] += v1;
        __syncthreads();
    }
    g_rowptr[t+1]    = s[t];
    g_rowptr[t+1025] = s[t+1024];
    if (t == 0) g_rowptr[0] = 0;
    g_cursor[t]      = (t == 0) ? 0 : s[t-1];
    g_cursor[t+1024] = s[t+1023];
}
__global__ void k_fill(const int* __restrict__ dst, int E){
    int i = blockIdx.x*256 + threadIdx.x;
    if (i < E){
        int p = atomicAdd(&g_cursor[dst[i]], 1);
        g_ceidx[p] = i;
    }
}

// ===================== mma-only radial MLP ========
#define SO_B1   0
#define SO_B2   8192
#define SO_BR1  16384
#define SO_BR2  16448
#define SO_W1T  16576
#define SM_FLOATS 16704
#define SM_BYTES  (SM_FLOATS*4)

__global__ void __launch_bounds__(128, 2)
k_mma_rad(const float* __restrict__ Wr1,
          const float* __restrict__ br1,
          const float* __restrict__ br2, int E, int layer){
    extern __shared__ float sm[];
    uint4* sB1 = (uint4*)(sm + SO_B1);
    uint4* sB2 = (uint4*)(sm + SO_B2);
    float* sbr1 = sm + SO_BR1;
    float* sbr2 = sm + SO_BR2;
    float* sW1t = sm + SO_W1T;
    int tid = threadIdx.x, w = tid >> 5, lane = tid & 31;

    const uint4* gB1 = g_B1t + layer*2048;
    const uint4* gB2 = g_B2t + layer*2048;
    #pragma unroll 4
    for (int i = tid; i < 2048; i += 128){ sB1[i] = gB1[i]; sB2[i] = gB2[i]; }
    if (tid < 64){
        sbr1[tid] = br1[tid];
        sW1t[tid]      = Wr1[128*64 + tid];
        sW1t[64 + tid] = Wr1[129*64 + tid];
    }
    if (tid < 128) sbr2[tid] = br2[tid];
    __syncthreads();

    float* radp = g_rad + (size_t)layer*EMAX*R4C;
    int nT = (E + 63) >> 6;
    int r0 = lane >> 2;
    int cb = (lane & 3)*2;

    for (int tt = blockIdx.x; tt < nT; tt += gridDim.x){
        int mc = tt*4 + w;
        size_t abase = (size_t)mc*4096 + lane*16;

        int tn = tt + gridDim.x;
        if (tn < nT){
            size_t pb = (size_t)(tn*4 + w)*4096 + lane*128;
            asm volatile("prefetch.global.L2 [%0];" :: "l"(g_a1h + pb));
            asm volatile("prefetch.global.L2 [%0];" :: "l"(g_a1l + pb));
        }

        float acc1[8][4];
        #pragma unroll
        for (int n = 0; n < 8; n++){ acc1[n][0]=0; acc1[n][1]=0; acc1[n][2]=0; acc1[n][3]=0; }
        #pragma unroll
        for (int kk = 0; kk < 8; kk++){
            uint4 Ah = *(const uint4*)(g_a1h + abase + kk*512);
            uint4 Al = *(const uint4*)(g_a1l + abase + kk*512);
            #pragma unroll
            for (int n = 0; n < 8; n++){
                uint4 B = sB1[(kk*8 + n)*32 + lane];
                MMA_BF16(acc1[n], Ah.x, Ah.y, Ah.z, Ah.w, B.x, B.y);
                MMA_BF16(acc1[n], Ah.x, Ah.y, Ah.z, Ah.w, B.z, B.w);
                MMA_BF16(acc1[n], Al.x, Al.y, Al.z, Al.w, B.x, B.y);
            }
        }

        int eg0 = mc*16 + r0, eg1 = eg0 + 8;
        float2 b0 = g_bpr[eg0];
        float2 b1 = g_bpr[eg1];
        uint32_t A2h[4][4], A2l[4][4];
        #pragma unroll
        for (int n = 0; n < 8; n++){
            int u0 = n*8 + cb, u1 = u0 + 1;
            float v00 = fmaxf(acc1[n][0] + sbr1[u0] + b0.x*sW1t[u0] + b0.y*sW1t[64+u0], 0.f);
            float v01 = fmaxf(acc1[n][1] + sbr1[u1] + b0.x*sW1t[u1] + b0.y*sW1t[64+u1], 0.f);
            float v10 = fmaxf(acc1[n][2] + sbr1[u0] + b1.x*sW1t[u0] + b1.y*sW1t[64+u0], 0.f);
            float v11 = fmaxf(acc1[n][3] + sbr1[u1] + b1.x*sW1t[u1] + b1.y*sW1t[64+u1], 0.f);
            float h00 = bf16hi(v00), h01 = bf16hi(v01), h10 = bf16hi(v10), h11 = bf16hi(v11);
            int kk2 = n >> 1;
            int hi2 = (n & 1) ? 2 : 0;
            A2h[kk2][hi2+0] = bf16pack(v00, v01);
            A2h[kk2][hi2+1] = bf16pack(v10, v11);
            A2l[kk2][hi2+0] = bf16pack(v00 - h00, v01 - h01);
            A2l[kk2][hi2+1] = bf16pack(v10 - h10, v11 - h11);
        }

        float acc2[16][4];
        #pragma unroll
        for (int n = 0; n < 16; n++){ acc2[n][0]=0; acc2[n][1]=0; acc2[n][2]=0; acc2[n][3]=0; }
        #pragma unroll
        for (int kk = 0; kk < 4; kk++){
            uint32_t ahx = A2h[kk][0], ahy = A2h[kk][1], ahz = A2h[kk][2], ahw = A2h[kk][3];
            uint32_t alx = A2l[kk][0], aly = A2l[kk][1], alz = A2l[kk][2], alw = A2l[kk][3];
            #pragma unroll
            for (int n = 0; n < 16; n++){
                uint4 B = sB2[(kk*16 + n)*32 + lane];
                MMA_BF16(acc2[n], ahx, ahy, ahz, ahw, B.x, B.y);
                MMA_BF16(acc2[n], ahx, ahy, ahz, ahw, B.z, B.w);
                MMA_BF16(acc2[n], alx, aly, alz, alw, B.x, B.y);
            }
        }

        bool ok0 = (eg0 < E), ok1 = (eg1 < E);
        float* row0 = radp + (size_t)eg0*R4C;
        float* row1 = radp + (size_t)eg1*R4C;
        #pragma unroll
        for (int n = 0; n < 16; n++){
            int col = n*8 + cb;
            float bb0 = sbr2[col], bb1 = sbr2[col+1];
            if (ok0) *(float2*)(row0 + col) = make_float2(acc2[n][0] + bb0, acc2[n][1] + bb1);
            if (ok1) *(float2*)(row1 + col) = make_float2(acc2[n][2] + bb0, acc2[n][3] + bb1);
        }
    }
}

// ---- slim tail: logits only ----
__global__ void k_tail(const int* __restrict__ esrc,
                       const int* __restrict__ edst, int E, int layer, int rb){
    const float* radp  = g_rad + (size_t)layer*EMAX*R4C;
    const float* a00r  = g_a00[rb];
    const float* g01rx = g_g01x[rb];
    const float* g01ry = g_g01y[rb];
    const float* g01rz = g_g01z[rb];
    int w = threadIdx.x >> 5, lane = threadIdx.x & 31;
    int ebase = blockIdx.x*128 + w*16;
    #pragma unroll 4
    for (int j = 0; j < 16; j++){
        int eg = ebase + j;
        if (eg >= E) break;
        const float* rrow = radp + (size_t)eg*R4C;
        float w00 = rrow[lane], w01 = rrow[32+lane];
        int s = esrc[eg], d = edst[eg];
        float rx = g_rhat[(size_t)eg*3+0];
        float ry = g_rhat[(size_t)eg*3+1];
        float rz = g_rhat[(size_t)eg*3+2];
        int sc = s*CV + lane;
        float gdot = g01rx[sc]*rx + g01ry[sc]*ry + g01rz[sc]*rz;
        float kc = w00*a00r[sc] + w01*gdot;
        float pq = g_q[d*CV+lane]*kc;
        pq += __shfl_down_sync(0xffffffffu, pq, 4);
        pq += __shfl_down_sync(0xffffffffu, pq, 2);
        pq += __shfl_down_sync(0xffffffffu, pq, 1);
        if ((lane & 7) == 0)
            g_logit[(size_t)eg*HV + (lane>>3)] = pq * 0.3535533906f;
    }
}

// ---- K4: softmax + aggregation (reads rad; 2 warps/node) + update + norms ----
__global__ void k_node_agg(const int* __restrict__ esrc,
                           const float* __restrict__ Wself0,
                           const float* __restrict__ Wself1,
                           const float* __restrict__ gamma0,
                           const float* __restrict__ beta0,
                           const float* __restrict__ gamma1,
                           const float* __restrict__ WqN,
                           const float* __restrict__ W00N,
                           const float* __restrict__ W10N,
                           const float* __restrict__ W01N,
                           const float* __restrict__ W11N,
                           int do_pre,
                           const float* __restrict__ Wout,
                           const float* __restrict__ coords,
                           float* __restrict__ out,
                           int do_final, int rb, int layer){
    __shared__ float sW0[1024], sW1[1024];
    __shared__ float sPq[1024], sP00[1024], sP10[1024], sP01[1024], sP11[1024];
    __shared__ float pa0[4][32], pax[4][32], pay[4][32], paz[4][32];
    int tid = threadIdx.x;
    for (int i = tid; i < 1024; i += 256){ sW0[i] = Wself0[i]; sW1[i] = Wself1[i]; }
    if (do_pre){
        for (int i = tid; i < 1024; i += 256){
            sPq[i] = WqN[i]; sP00[i] = W00N[i]; sP10[i] = W10N[i];
            sP01[i] = W01N[i]; sP11[i] = W11N[i];
        }
    }
    __syncthreads();
    const float* radp  = g_rad + (size_t)layer*EMAX*R4C;
    const float* a00r  = g_a00[rb];
    const float* a10r  = g_a10[rb];
    const float* g01rx = g_g01x[rb];
    const float* g01ry = g_g01y[rb];
    const float* g01rz = g_g01z[rb];
    const float* g11rx = g_g11x[rb];
    const float* g11ry = g_g11y[rb];
    const float* g11rz = g_g11z[rb];
    int w = tid >> 5, lane = tid & 31;
    int p = w >> 1, half = w & 1;
    int n = blockIdx.x*4 + p;
    int rp = g_rowptr[n], deg = g_rowptr[n+1] - rp;

    float mx = -1e30f;
    for (int j0 = 0; j0 < deg; j0 += 8){
        int j = j0 + (lane >> 2);
        if (j < deg){
            int e = g_ceidx[rp + j];
            mx = fmaxf(mx, g_logit[(size_t)e*HV + (lane & 3)]);
        }
    }
    mx = fmaxf(mx, __shfl_xor_sync(0xffffffffu, mx, 4));
    mx = fmaxf(mx, __shfl_xor_sync(0xffffffffu, mx, 8));
    mx = fmaxf(mx, __shfl_xor_sync(0xffffffffu, mx, 16));
    if (mx < -1e29f) mx = 0.f;
    float den = 0.f;
    for (int j0 = 0; j0 < deg; j0 += 8){
        int j = j0 + (lane >> 2);
        if (j < deg){
            int e = g_ceidx[rp + j];
            den += expf(g_logit[(size_t)e*HV + (lane & 3)] - mx);
        }
    }
    den += __shfl_xor_sync(0xffffffffu, den, 4);
    den += __shfl_xor_sync(0xffffffffu, den, 8);
    den += __shfl_xor_sync(0xffffffffu, den, 16);
    float mxh  = __shfl_sync(0xffffffffu, mx,  lane >> 3);
    float dinv = 1.f / (__shfl_sync(0xffffffffu, den, lane >> 3) + 1e-9f);

    float a0=0.f, ax=0.f, ay=0.f, az=0.f;
    for (int j = half; j < deg; j += 2){
        int e = g_ceidx[rp + j];
        float alpha = expf(g_logit[(size_t)e*HV + (lane>>3)] - mxh) * dinv;
        const float* rrow = radp + (size_t)e*R4C;
        float w00 = rrow[lane], w01 = rrow[32+lane], w10 = rrow[64+lane], w11 = rrow[96+lane];
        float rx = g_rhat[(size_t)e*3+0];
        float ry = g_rhat[(size_t)e*3+1];
        float rz = g_rhat[(size_t)e*3+2];
        int s  = esrc[e];
        int sc = s*CV + lane;
        float gdot = g01rx[sc]*rx + g01ry[sc]*ry + g01rz[sc]*rz;
        float kc = w00*a00r[sc] + w01*gdot;
        a0 += alpha * kc;
        float s10 = w10*a10r[sc];
        ax += alpha * (w11*g11rx[sc] + s10*rx);
        ay += alpha * (w11*g11ry[sc] + s10*ry);
        az += alpha * (w11*g11rz[sc] + s10*rz);
    }
    if (half == 1){
        pa0[p][lane] = a0; pax[p][lane] = ax; pay[p][lane] = ay; paz[p][lane] = az;
    }
    __syncthreads();
    if (half == 1) return;
    a0 += pa0[p][lane]; ax += pax[p][lane]; ay += pay[p][lane]; az += paz[p][lane];

    float nh0 = g_h0 [n*CV + lane];
    float x   = g_h1x[n*CV + lane];
    float y   = g_h1y[n*CV + lane];
    float z   = g_h1z[n*CV + lane];
    #pragma unroll 8
    for (int c = 0; c < CV; c++){
        float b0 = __shfl_sync(0xffffffffu, a0, c);
        float bx = __shfl_sync(0xffffffffu, ax, c);
        float by = __shfl_sync(0xffffffffu, ay, c);
        float bz = __shfl_sync(0xffffffffu, az, c);
        float w0 = sW0[c*CV+lane], w1 = sW1[c*CV+lane];
        nh0 += b0*w0;
        x += bx*w1; y += by*w1; z += bz*w1;
    }
    float mu  = warpsum(nh0) * (1.f/32.f);
    float dv  = nh0 - mu;
    float var = warpsum(dv*dv) * (1.f/32.f);
    float h0new = dv*rsqrtf(var + 1e-5f)*gamma0[lane] + beta0[lane];
    g_h0[n*CV+lane] = h0new;
    float nrm  = sqrtf(x*x + y*y + z*z + 1e-12f);
    float mun  = warpsum(nrm) * (1.f/32.f);
    float dn   = nrm - mun;
    float varn = warpsum(dn*dn) * (1.f/32.f);
    float nln  = dn*rsqrtf(varn + 1e-5f)*gamma1[lane];
    float sc   = nln / (nrm + 1e-8f);
    float hx = x*sc, hy = y*sc, hz = z*sc;
    g_h1x[n*CV+lane] = hx;
    g_h1y[n*CV+lane] = hy;
    g_h1z[n*CV+lane] = hz;

    if (do_pre){
        float q=0, p00=0, p10=0;
        float g01x=0,g01y=0,g01z=0,g11x=0,g11y=0,g11z=0;
        #pragma unroll 8
        for (int c = 0; c < CV; c++){
            float hc  = __shfl_sync(0xffffffffu, h0new, c);
            float hcx = __shfl_sync(0xffffffffu, hx, c);
            float hcy = __shfl_sync(0xffffffffu, hy, c);
            float hcz = __shfl_sync(0xffffffffu, hz, c);
            q   += hc*sPq [c*CV+lane];
            p00 += hc*sP00[c*CV+lane];
            p10 += hc*sP10[c*CV+lane];
            float w01 = sP01[c*CV+lane], w11 = sP11[c*CV+lane];
            g01x += hcx*w01; g01y += hcy*w01; g01z += hcz*w01;
            g11x += hcx*w11; g11y += hcy*w11; g11z += hcz*w11;
        }
        int wb = rb ^ 1;
        g_q  [n*CV+lane] = q;
        g_a00[wb][n*CV+lane] = p00;
        g_a10[wb][n*CV+lane] = p10;
        g_g01x[wb][n*CV+lane]=g01x; g_g01y[wb][n*CV+lane]=g01y; g_g01z[wb][n*CV+lane]=g01z;
        g_g11x[wb][n*CV+lane]=g11x; g_g11y[wb][n*CV+lane]=g11y; g_g11z[wb][n*CV+lane]=g11z;
    }
    if (do_final){
        float wo = Wout[lane];
        float dx = warpsum(hx*wo);
        float dy = warpsum(hy*wo);
        float dz = warpsum(hz*wo);
        if (lane == 0){
            out[n*3+0] = coords[n*3+0] + dx;
            out[n*3+1] = coords[n*3+1] + dy;
            out[n*3+2] = coords[n*3+2] + dz;
        }
    }
}

extern "C" void kernel_launch(void* const* d_in, const int* in_sizes, int n_in,
                              void* d_out, int out_size){
    const float* seq    = (const float*)d_in[0];
    const float* pair   = (const float*)d_in[1];
    const float* bppm   = (const float*)d_in[2];
    const float* coords = (const float*)d_in[3];
    const int*   esrc   = (const int*)  d_in[4];
    const int*   edst   = (const int*)  d_in[5];
    const float* Win0   = (const float*)d_in[6];
    const float* Win1   = (const float*)d_in[7];
    const float* Wr1    = (const float*)d_in[8];
    const float* br1    = (const float*)d_in[9];
    const float* Wr2    = (const float*)d_in[10];
    const float* br2    = (const float*)d_in[11];
    const float* Wm00   = (const float*)d_in[12];
    const float* Wm01   = (const float*)d_in[13];
    const float* Wm10   = (const float*)d_in[14];
    const float* Wm11   = (const float*)d_in[15];
    const float* Wq     = (const float*)d_in[16];
    const float* Wself0 = (const float*)d_in[17];
    const float* Wself1 = (const float*)d_in[18];
    const float* gamma0 = (const float*)d_in[19];
    const float* beta0  = (const float*)d_in[20];
    const float* gamma1 = (const float*)d_in[21];
    const float* Wout   = (const float*)d_in[22];

    int E = in_sizes[4];
    if (E > EMAX) E = EMAX;

    static cudaStream_t s2 = nullptr;
    static cudaEvent_t evRoot = nullptr, evSetup = nullptr, evBtab = nullptr;
    static cudaEvent_t evM[NLV] = {nullptr, nullptr, nullptr};
    if (s2 == nullptr){
        cudaStreamCreateWithFlags(&s2, cudaStreamNonBlocking);
        cudaEventCreateWithFlags(&evRoot,  cudaEventDisableTiming);
        cudaEventCreateWithFlags(&evSetup, cudaEventDisableTiming);
        cudaEventCreateWithFlags(&evBtab,  cudaEventDisableTiming);
        for (int l = 0; l < NLV; l++)
            cudaEventCreateWithFlags(&evM[l], cudaEventDisableTiming);
        cudaFuncSetAttribute(k_mma_rad,
            cudaFuncAttributeMaxDynamicSharedMemorySize, SM_BYTES);
        cudaFuncSetAttribute(k_init_nodes,
            cudaFuncAttributeMaxDynamicSharedMemorySize, (20480+16*D0V)*4);
    }

    // side stream: edge setup first
    cudaEventRecord(evRoot, 0);
    cudaStreamWaitEvent(s2, evRoot, 0);
    k_edge_setup<<<1480, 256, 0, s2>>>(coords, pair, bppm, esrc, edst, E);    // #1
    cudaEventRecord(evSetup, s2);

    // main head: B tables first so MMA can start ASAP
    k_btab<<<24, 256>>>(Wr1, Wr2);                                            // #2
    cudaEventRecord(evBtab, 0);
    k_init_nodes<<<128, 512, (20480+16*D0V)*4>>>(seq, coords, Win0, Win1);    // #3
    k_node_pre<<<128, 256>>>(Wq, Wm00, Wm10, Wm01, Wm11);                     // #4

    // side stream: all 3 layers' radial GEMMs (need setup + btab only)
    cudaStreamWaitEvent(s2, evBtab, 0);
    for (int l = 0; l < NLV; l++){
        k_mma_rad<<<296, 128, SM_BYTES, s2>>>(Wr1 + l*RADIN*HIDV,
            br1 + l*HIDV, br2 + l*R4C, E, l);
        cudaEventRecord(evM[l], s2);
    }

    // main: CSR, then per-layer tail+agg
    cudaStreamWaitEvent(0, evSetup, 0);
    k_scan<<<1, 1024>>>(E);
    k_fill<<<(E+255)/256, 256>>>(edst, E);

    for (int l = 0; l < NLV; l++){
        int lp = l + 1;
        int rb = l & 1;
        int do_pre = (l < NLV-1);
        int do_fin = (l == NLV-1);
        cudaStreamWaitEvent(0, evM[l], 0);
        k_tail<<<(E+127)/128, 256>>>(esrc, edst, E, l, rb);
        k_node_agg<<<512, 256>>>(esrc,
            Wself0 + l*CV*CV, Wself1 + l*CV*CV,
            gamma0 + l*CV, beta0 + l*CV, gamma1 + l*CV,
            Wq + (do_pre ? lp*CV*CV : 0), Wm00 + (do_pre ? lp*CV*CV : 0),
            Wm10 + (do_pre ? lp*CV*CV : 0), Wm01 + (do_pre ? lp*CV*CV : 0),
            Wm11 + (do_pre ? lp*CV*CV : 0), do_pre,
            Wout, coords, (float*)d_out, do_fin, rb, l);
    }
}

// round 17
// speedup vs baseline: 1.1357x; 1.1357x over previous
#include <cuda_runtime.h>
#include <cuda_bf16.h>
#include <math.h>
#include <stdint.h>

// ---- problem constants ----
#define NB    4
#define LL    512
#define NNODE 2048
#define D0V   640
#define PV    128
#define CV    32
#define HV    4
#define NLV   3
#define RADIN 130
#define HIDV  64
#define R4C   128
#define EMAX  262144

typedef unsigned long long ull;

// ---- device scratch ----
__device__ float g_h0  [NNODE*CV];
__device__ float g_h1x [NNODE*CV];
__device__ float g_h1y [NNODE*CV];
__device__ float g_h1z [NNODE*CV];
__device__ float g_q   [NNODE*CV];
__device__ float g_a00 [NNODE*CV];
__device__ float g_a10 [NNODE*CV];
__device__ float g_g01x[NNODE*CV];
__device__ float g_g01y[NNODE*CV];
__device__ float g_g01z[NNODE*CV];
__device__ float g_g11x[2][NNODE*CV];
__device__ float g_g11y[2][NNODE*CV];
__device__ float g_g11z[2][NNODE*CV];
__device__ unsigned char g_a1h[(size_t)(EMAX/16)*4096];
__device__ unsigned char g_a1l[(size_t)(EMAX/16)*4096];
__device__ uint4 g_B1t[NLV*2048];
__device__ uint4 g_B2t[NLV*2048];
__device__ float g_rad [(size_t)NLV*EMAX*R4C];
__device__ float2 g_bpr[EMAX];
__device__ float g_rhat[(size_t)EMAX*3];
__device__ float g_k   [(size_t)EMAX*CV];
__device__ float g_s10 [(size_t)EMAX*CV];
__device__ float g_w11e[(size_t)EMAX*CV];
__device__ float g_logit[(size_t)EMAX*HV];
__device__ int   g_deg   [NNODE];
__device__ int   g_rowptr[NNODE+1];
__device__ int   g_cursor[NNODE];
__device__ int   g_ceidx [EMAX];

// ---- helpers ----
__device__ __forceinline__ float warpsum(float v){
    #pragma unroll
    for (int o = 16; o; o >>= 1) v += __shfl_xor_sync(0xffffffffu, v, o);
    return v;
}
__device__ __forceinline__ uint32_t bf16pack(float a, float b){
    __nv_bfloat162 t = __floats2bfloat162_rn(a, b);
    return *(uint32_t*)&t;
}
__device__ __forceinline__ float bf16hi(float a){
    return __bfloat162float(__float2bfloat16_rn(a));
}

#define MMA_BF16(c, ax, ay, az, aw, b0, b1) \
    asm volatile("mma.sync.aligned.m16n8k16.row.col.f32.bf16.bf16.f32 " \
        "{%0,%1,%2,%3}, {%4,%5,%6,%7}, {%8,%9}, {%0,%1,%2,%3};" \
        : "+f"((c)[0]), "+f"((c)[1]), "+f"((c)[2]), "+f"((c)[3]) \
        : "r"(ax), "r"(ay), "r"(az), "r"(aw), "r"(b0), "r"(b1))

// ---- B fragment tables (all layers) ----
__global__ void k_btab(const float* __restrict__ Wr1all,
                       const float* __restrict__ Wr2all){
    int gidx = blockIdx.x*256 + threadIdx.x;
    int gstride = gridDim.x*256;
    for (int idx = gidx; idx < NLV*2048; idx += gstride){
        int l = idx >> 11, t = idx & 2047;
        int lf = t & 31, nt = (t >> 5) & 7, kk = t >> 8;
        int n  = nt*8 + (lf >> 2);
        int k0 = kk*16 + (lf & 3)*2;
        const float* W = Wr1all + l*RADIN*HIDV;
        float v0 = W[k0*64 + n],     v1 = W[(k0+1)*64 + n];
        float v2 = W[(k0+8)*64 + n], v3 = W[(k0+9)*64 + n];
        uint4 val;
        val.x = bf16pack(v0, v1);
        val.y = bf16pack(v2, v3);
        val.z = bf16pack(v0 - bf16hi(v0), v1 - bf16hi(v1));
        val.w = bf16pack(v2 - bf16hi(v2), v3 - bf16hi(v3));
        g_B1t[idx] = val;
    }
    for (int idx = gidx; idx < NLV*2048; idx += gstride){
        int l = idx >> 11, t = idx & 2047;
        int lf = t & 31, nt = (t >> 5) & 15, kk = t >> 9;
        int n  = nt*8 + (lf >> 2);
        int k0 = kk*16 + (lf & 3)*2;
        const float* W = Wr2all + l*HIDV*R4C;
        float v0 = W[k0*128 + n],     v1 = W[(k0+1)*128 + n];
        float v2 = W[(k0+8)*128 + n], v3 = W[(k0+9)*128 + n];
        uint4 val;
        val.x = bf16pack(v0, v1);
        val.y = bf16pack(v2, v3);
        val.z = bf16pack(v0 - bf16hi(v0), v1 - bf16hi(v1));
        val.w = bf16pack(v2 - bf16hi(v2), v3 - bf16hi(v3));
        g_B2t[idx] = val;
    }
}

// ---- K0: h0 = seq @ Win0 ; h1 = x * Win1 ----
__global__ void k_init_nodes(const float* __restrict__ seq,
                             const float* __restrict__ coords,
                             const float* __restrict__ Win0,
                             const float* __restrict__ Win1){
    extern __shared__ float sm[];
    float* sW   = sm;
    float* sSeq = sm + 20480;
    int tid = threadIdx.x;
    for (int i = tid; i < D0V*CV; i += 512) sW[i] = Win0[i];
    int n0 = blockIdx.x * 16;
    for (int i = tid; i < 16*D0V; i += 512) sSeq[i] = seq[(size_t)n0*D0V + i];
    __syncthreads();
    int w = tid >> 5, lane = tid & 31;
    int n = n0 + w;
    const float* srow = sSeq + w*D0V;
    float acc = 0.f;
    #pragma unroll 4
    for (int i = 0; i < D0V; i++) acc += srow[i]*sW[i*CV + lane];
    g_h0[n*CV + lane] = acc;
    float wv = Win1[lane];
    g_h1x[n*CV+lane] = coords[n*3+0]*wv;
    g_h1y[n*CV+lane] = coords[n*3+1]*wv;
    g_h1z[n*CV+lane] = coords[n*3+2]*wv;
}

// ---- K1: geometry + fragment-major bf16 hi/lo A tiles + (bppm,r) + deg ----
__global__ void k_edge_setup(const float* __restrict__ coords,
                             const float* __restrict__ pair,
                             const float* __restrict__ bppm,
                             const int* __restrict__ src,
                             const int* __restrict__ dst, int E){
    int w = threadIdx.x >> 5, lane = threadIdx.x & 31;
    for (int e = blockIdx.x*8 + w; e < E; e += gridDim.x*8){
        int s = src[e], d = dst[e];
        int di = d & (LL-1);
        if (lane == 0){
            atomicAdd(&g_deg[d], 1);
            float rx = coords[d*3+0]-coords[s*3+0];
            float ry = coords[d*3+1]-coords[s*3+1];
            float rz = coords[d*3+2]-coords[s*3+2];
            float r  = sqrtf(rx*rx + ry*ry + rz*rz + 1e-12f);
            float inv = 1.f/(r + 1e-8f);
            g_rhat[(size_t)e*3+0] = rx*inv;
            g_rhat[(size_t)e*3+1] = ry*inv;
            g_rhat[(size_t)e*3+2] = rz*inv;
            g_bpr[e] = make_float2(bppm[(size_t)s*LL + di], r);
        }
        float4 pv = ((const float4*)(pair + ((size_t)s*LL + di)*PV))[lane];
        float h0 = bf16hi(pv.x), h1 = bf16hi(pv.y), h2 = bf16hi(pv.z), h3 = bf16hi(pv.w);
        uint32_t w0h = bf16pack(pv.x, pv.y);
        uint32_t w1h = bf16pack(pv.z, pv.w);
        uint32_t w0l = bf16pack(pv.x - h0, pv.y - h1);
        uint32_t w1l = bf16pack(pv.z - h2, pv.w - h3);
        int mc = e >> 4, r = e & 15;
        int kk = lane >> 2, m4 = lane & 3;
        int regb = (m4 < 2) ? 0 : 2;
        int reg  = regb + ((r < 8) ? 0 : 1);
        int lt01 = (r & 7)*4 + (m4 & 1)*2;
        int lt23 = lt01 + 1;
        size_t base = (size_t)mc*4096 + (size_t)kk*512;
        *(uint32_t*)(g_a1h + base + lt01*16 + reg*4) = w0h;
        *(uint32_t*)(g_a1h + base + lt23*16 + reg*4) = w1h;
        *(uint32_t*)(g_a1l + base + lt01*16 + reg*4) = w0l;
        *(uint32_t*)(g_a1l + base + lt23*16 + reg*4) = w1l;
    }
}

// ---- K2: per-node precompute (layer 0) ----
__global__ void k_node_pre(const float* __restrict__ Wq,
                           const float* __restrict__ Wm00,
                           const float* __restrict__ Wm10,
                           const float* __restrict__ Wm01,
                           const float* __restrict__ Wm11){
    __shared__ float sWq[1024], s00[1024], s10w[1024], s01[1024], s11[1024];
    int tid = threadIdx.x;
    for (int i = tid; i < 1024; i += 256){
        sWq[i] = Wq[i]; s00[i] = Wm00[i]; s10w[i] = Wm10[i];
        s01[i] = Wm01[i]; s11[i] = Wm11[i];
    }
    __syncthreads();
    int w = tid >> 5, lane = tid & 31;
    for (int n = blockIdx.x*8 + w; n < NNODE; n += gridDim.x*8){
        float h  = g_h0 [n*CV + lane];
        float hx = g_h1x[n*CV + lane];
        float hy = g_h1y[n*CV + lane];
        float hz = g_h1z[n*CV + lane];
        float q=0, a00=0, a10=0;
        float g01x=0,g01y=0,g01z=0,g11x=0,g11y=0,g11z=0;
        #pragma unroll 8
        for (int c = 0; c < CV; c++){
            float hc  = __shfl_sync(0xffffffffu, h,  c);
            float hcx = __shfl_sync(0xffffffffu, hx, c);
            float hcy = __shfl_sync(0xffffffffu, hy, c);
            float hcz = __shfl_sync(0xffffffffu, hz, c);
            q   += hc*sWq [c*CV+lane];
            a00 += hc*s00 [c*CV+lane];
            a10 += hc*s10w[c*CV+lane];
            float w01 = s01[c*CV+lane], w11 = s11[c*CV+lane];
            g01x += hcx*w01; g01y += hcy*w01; g01z += hcz*w01;
            g11x += hcx*w11; g11y += hcy*w11; g11z += hcz*w11;
        }
        g_q  [n*CV+lane] = q;
        g_a00[n*CV+lane] = a00;
        g_a10[n*CV+lane] = a10;
        g_g01x[n*CV+lane]=g01x; g_g01y[n*CV+lane]=g01y; g_g01z[n*CV+lane]=g01z;
        g_g11x[0][n*CV+lane]=g11x; g_g11y[0][n*CV+lane]=g11y; g_g11z[0][n*CV+lane]=g11z;
    }
}

// ---- CSR scan (+ deg reset) + fill ----
__global__ void k_scan(int E){
    __shared__ int s[NNODE];
    int t = threadIdx.x;
    s[t] = g_deg[t]; s[t+1024] = g_deg[t+1024];
    g_deg[t] = 0; g_deg[t+1024] = 0;
    __syncthreads();
    for (int off = 1; off < NNODE; off <<= 1){
        int v0 = (t >= off) ? s[t-off] : 0;
        int i1 = t + 1024;
        int v1 = (i1 >= off) ? s[i1-off] : 0;
        __syncthreads();
        s[t] += v0; s[i1] += v1;
        __syncthreads();
    }
    g_rowptr[t+1]    = s[t];
    g_rowptr[t+1025] = s[t+1024];
    if (t == 0) g_rowptr[0] = 0;
    g_cursor[t]      = (t == 0) ? 0 : s[t-1];
    g_cursor[t+1024] = s[t+1023];
}
__global__ void k_fill(const int* __restrict__ dst, int E){
    int i = blockIdx.x*256 + threadIdx.x;
    if (i < E){
        int p = atomicAdd(&g_cursor[dst[i]], 1);
        g_ceidx[p] = i;
    }
}

// ===================== mma-only radial MLP ========
#define SO_B1   0
#define SO_B2   8192
#define SO_BR1  16384
#define SO_BR2  16448
#define SO_W1T  16576
#define SM_FLOATS 16704
#define SM_BYTES  (SM_FLOATS*4)

__global__ void __launch_bounds__(128, 2)
k_mma_rad(const float* __restrict__ Wr1,
          const float* __restrict__ br1,
          const float* __restrict__ br2, int E, int layer){
    extern __shared__ float sm[];
    uint4* sB1 = (uint4*)(sm + SO_B1);
    uint4* sB2 = (uint4*)(sm + SO_B2);
    float* sbr1 = sm + SO_BR1;
    float* sbr2 = sm + SO_BR2;
    float* sW1t = sm + SO_W1T;
    int tid = threadIdx.x, w = tid >> 5, lane = tid & 31;

    const uint4* gB1 = g_B1t + layer*2048;
    const uint4* gB2 = g_B2t + layer*2048;
    #pragma unroll 4
    for (int i = tid; i < 2048; i += 128){ sB1[i] = gB1[i]; sB2[i] = gB2[i]; }
    if (tid < 64){
        sbr1[tid] = br1[tid];
        sW1t[tid]      = Wr1[128*64 + tid];
        sW1t[64 + tid] = Wr1[129*64 + tid];
    }
    if (tid < 128) sbr2[tid] = br2[tid];
    __syncthreads();

    float* radp = g_rad + (size_t)layer*EMAX*R4C;
    int nT = (E + 63) >> 6;
    int r0 = lane >> 2;
    int cb = (lane & 3)*2;

    for (int tt = blockIdx.x; tt < nT; tt += gridDim.x){
        int mc = tt*4 + w;
        size_t abase = (size_t)mc*4096 + lane*16;

        int tn = tt + gridDim.x;
        if (tn < nT){
            size_t pb = (size_t)(tn*4 + w)*4096 + lane*128;
            asm volatile("prefetch.global.L2 [%0];" :: "l"(g_a1h + pb));
            asm volatile("prefetch.global.L2 [%0];" :: "l"(g_a1l + pb));
        }

        float acc1[8][4];
        #pragma unroll
        for (int n = 0; n < 8; n++){ acc1[n][0]=0; acc1[n][1]=0; acc1[n][2]=0; acc1[n][3]=0; }
        #pragma unroll
        for (int kk = 0; kk < 8; kk++){
            uint4 Ah = *(const uint4*)(g_a1h + abase + kk*512);
            uint4 Al = *(const uint4*)(g_a1l + abase + kk*512);
            #pragma unroll
            for (int n = 0; n < 8; n++){
                uint4 B = sB1[(kk*8 + n)*32 + lane];
                MMA_BF16(acc1[n], Ah.x, Ah.y, Ah.z, Ah.w, B.x, B.y);
                MMA_BF16(acc1[n], Ah.x, Ah.y, Ah.z, Ah.w, B.z, B.w);
                MMA_BF16(acc1[n], Al.x, Al.y, Al.z, Al.w, B.x, B.y);
            }
        }

        int eg0 = mc*16 + r0, eg1 = eg0 + 8;
        float2 b0 = g_bpr[eg0];
        float2 b1 = g_bpr[eg1];
        uint32_t A2h[4][4], A2l[4][4];
        #pragma unroll
        for (int n = 0; n < 8; n++){
            int u0 = n*8 + cb, u1 = u0 + 1;
            float v00 = fmaxf(acc1[n][0] + sbr1[u0] + b0.x*sW1t[u0] + b0.y*sW1t[64+u0], 0.f);
            float v01 = fmaxf(acc1[n][1] + sbr1[u1] + b0.x*sW1t[u1] + b0.y*sW1t[64+u1], 0.f);
            float v10 = fmaxf(acc1[n][2] + sbr1[u0] + b1.x*sW1t[u0] + b1.y*sW1t[64+u0], 0.f);
            float v11 = fmaxf(acc1[n][3] + sbr1[u1] + b1.x*sW1t[u1] + b1.y*sW1t[64+u1], 0.f);
            float h00 = bf16hi(v00), h01 = bf16hi(v01), h10 = bf16hi(v10), h11 = bf16hi(v11);
            int kk2 = n >> 1;
            int hi2 = (n & 1) ? 2 : 0;
            A2h[kk2][hi2+0] = bf16pack(v00, v01);
            A2h[kk2][hi2+1] = bf16pack(v10, v11);
            A2l[kk2][hi2+0] = bf16pack(v00 - h00, v01 - h01);
            A2l[kk2][hi2+1] = bf16pack(v10 - h10, v11 - h11);
        }

        float acc2[16][4];
        #pragma unroll
        for (int n = 0; n < 16; n++){ acc2[n][0]=0; acc2[n][1]=0; acc2[n][2]=0; acc2[n][3]=0; }
        #pragma unroll
        for (int kk = 0; kk < 4; kk++){
            uint32_t ahx = A2h[kk][0], ahy = A2h[kk][1], ahz = A2h[kk][2], ahw = A2h[kk][3];
            uint32_t alx = A2l[kk][0], aly = A2l[kk][1], alz = A2l[kk][2], alw = A2l[kk][3];
            #pragma unroll
            for (int n = 0; n < 16; n++){
                uint4 B = sB2[(kk*16 + n)*32 + lane];
                MMA_BF16(acc2[n], ahx, ahy, ahz, ahw, B.x, B.y);
                MMA_BF16(acc2[n], ahx, ahy, ahz, ahw, B.z, B.w);
                MMA_BF16(acc2[n], alx, aly, alz, alw, B.x, B.y);
            }
        }

        bool ok0 = (eg0 < E), ok1 = (eg1 < E);
        float* row0 = radp + (size_t)eg0*R4C;
        float* row1 = radp + (size_t)eg1*R4C;
        #pragma unroll
        for (int n = 0; n < 16; n++){
            int col = n*8 + cb;
            float bb0 = sbr2[col], bb1 = sbr2[col+1];
            if (ok0) *(float2*)(row0 + col) = make_float2(acc2[n][0] + bb0, acc2[n][1] + bb1);
            if (ok1) *(float2*)(row1 + col) = make_float2(acc2[n][2] + bb0, acc2[n][3] + bb1);
        }
    }
}

// ---- tail: messages + logits from rad (round-15 structure) ----
__global__ void k_tail(const int* __restrict__ esrc,
                       const int* __restrict__ edst, int E, int layer){
    const float* radp = g_rad + (size_t)layer*EMAX*R4C;
    int w = threadIdx.x >> 5, lane = threadIdx.x & 31;
    int ebase = blockIdx.x*128 + w*16;
    #pragma unroll 4
    for (int j = 0; j < 16; j++){
        int eg = ebase + j;
        if (eg >= E) break;
        const float* rrow = radp + (size_t)eg*R4C;
        float w00 = rrow[lane], w01 = rrow[32+lane], w10 = rrow[64+lane], w11 = rrow[96+lane];
        int s = esrc[eg], d = edst[eg];
        float rx = g_rhat[(size_t)eg*3+0];
        float ry = g_rhat[(size_t)eg*3+1];
        float rz = g_rhat[(size_t)eg*3+2];
        int sc = s*CV + lane;
        float gdot = g_g01x[sc]*rx + g_g01y[sc]*ry + g_g01z[sc]*rz;
        float kc = w00*g_a00[sc] + w01*gdot;
        size_t ec = (size_t)eg*CV + lane;
        g_k[ec]    = kc;
        g_s10[ec]  = w10*g_a10[sc];
        g_w11e[ec] = w11;
        float pq = g_q[d*CV+lane]*kc;
        pq += __shfl_down_sync(0xffffffffu, pq, 4);
        pq += __shfl_down_sync(0xffffffffu, pq, 2);
        pq += __shfl_down_sync(0xffffffffu, pq, 1);
        if ((lane & 7) == 0)
            g_logit[(size_t)eg*HV + (lane>>3)] = pq * 0.3535533906f;
    }
}

// ---- K4: softmax + aggregation (2 warps/node) + update + norms (+ pre/final) ----
__global__ void k_node_agg(const int* __restrict__ esrc,
                           const float* __restrict__ Wself0,
                           const float* __restrict__ Wself1,
                           const float* __restrict__ gamma0,
                           const float* __restrict__ beta0,
                           const float* __restrict__ gamma1,
                           const float* __restrict__ WqN,
                           const float* __restrict__ W00N,
                           const float* __restrict__ W10N,
                           const float* __restrict__ W01N,
                           const float* __restrict__ W11N,
                           int do_pre,
                           const float* __restrict__ Wout,
                           const float* __restrict__ coords,
                           float* __restrict__ out,
                           int do_final, int rb){
    __shared__ float sW0[1024], sW1[1024];
    __shared__ float sPq[1024], sP00[1024], sP10[1024], sP01[1024], sP11[1024];
    __shared__ float pa0[4][32], pax[4][32], pay[4][32], paz[4][32];
    int tid = threadIdx.x;
    for (int i = tid; i < 1024; i += 256){ sW0[i] = Wself0[i]; sW1[i] = Wself1[i]; }
    if (do_pre){
        for (int i = tid; i < 1024; i += 256){
            sPq[i] = WqN[i]; sP00[i] = W00N[i]; sP10[i] = W10N[i];
            sP01[i] = W01N[i]; sP11[i] = W11N[i];
        }
    }
    __syncthreads();
    const float* g11rx = g_g11x[rb];
    const float* g11ry = g_g11y[rb];
    const float* g11rz = g_g11z[rb];
    float* g11wx = g_g11x[rb^1];
    float* g11wy = g_g11y[rb^1];
    float* g11wz = g_g11z[rb^1];
    int w = tid >> 5, lane = tid & 31;
    int p = w >> 1, half = w & 1;
    int n = blockIdx.x*4 + p;
    int rp = g_rowptr[n], deg = g_rowptr[n+1] - rp;

    float mx = -1e30f;
    for (int j0 = 0; j0 < deg; j0 += 8){
        int j = j0 + (lane >> 2);
        if (j < deg){
            int e = g_ceidx[rp + j];
            mx = fmaxf(mx, g_logit[(size_t)e*HV + (lane & 3)]);
        }
    }
    mx = fmaxf(mx, __shfl_xor_sync(0xffffffffu, mx, 4));
    mx = fmaxf(mx, __shfl_xor_sync(0xffffffffu, mx, 8));
    mx = fmaxf(mx, __shfl_xor_sync(0xffffffffu, mx, 16));
    if (mx < -1e29f) mx = 0.f;
    float den = 0.f;
    for (int j0 = 0; j0 < deg; j0 += 8){
        int j = j0 + (lane >> 2);
        if (j < deg){
            int e = g_ceidx[rp + j];
            den += expf(g_logit[(size_t)e*HV + (lane & 3)] - mx);
        }
    }
    den += __shfl_xor_sync(0xffffffffu, den, 4);
    den += __shfl_xor_sync(0xffffffffu, den, 8);
    den += __shfl_xor_sync(0xffffffffu, den, 16);
    float mxh  = __shfl_sync(0xffffffffu, mx,  lane >> 3);
    float dinv = 1.f / (__shfl_sync(0xffffffffu, den, lane >> 3) + 1e-9f);

    float a0=0.f, ax=0.f, ay=0.f, az=0.f;
    for (int j = half; j < deg; j += 2){
        int e = g_ceidx[rp + j];
        float alpha = expf(g_logit[(size_t)e*HV + (lane>>3)] - mxh) * dinv;
        size_t ec = (size_t)e*CV + lane;
        float kc = g_k[ec];
        a0 += alpha * kc;
        float s10 = g_s10[ec], w11 = g_w11e[ec];
        float rx = g_rhat[(size_t)e*3+0];
        float ry = g_rhat[(size_t)e*3+1];
        float rz = g_rhat[(size_t)e*3+2];
        int s  = esrc[e];
        int sc = s*CV + lane;
        ax += alpha * (w11*g11rx[sc] + s10*rx);
        ay += alpha * (w11*g11ry[sc] + s10*ry);
        az += alpha * (w11*g11rz[sc] + s10*rz);
    }
    if (half == 1){
        pa0[p][lane] = a0; pax[p][lane] = ax; pay[p][lane] = ay; paz[p][lane] = az;
    }
    __syncthreads();
    if (half == 1) return;
    a0 += pa0[p][lane]; ax += pax[p][lane]; ay += pay[p][lane]; az += paz[p][lane];

    float nh0 = g_h0 [n*CV + lane];
    float x   = g_h1x[n*CV + lane];
    float y   = g_h1y[n*CV + lane];
    float z   = g_h1z[n*CV + lane];
    #pragma unroll 8
    for (int c = 0; c < CV; c++){
        float b0 = __shfl_sync(0xffffffffu, a0, c);
        float bx = __shfl_sync(0xffffffffu, ax, c);
        float by = __shfl_sync(0xffffffffu, ay, c);
        float bz = __shfl_sync(0xffffffffu, az, c);
        float w0 = sW0[c*CV+lane], w1 = sW1[c*CV+lane];
        nh0 += b0*w0;
        x += bx*w1; y += by*w1; z += bz*w1;
    }
    float mu  = warpsum(nh0) * (1.f/32.f);
    float dv  = nh0 - mu;
    float var = warpsum(dv*dv) * (1.f/32.f);
    float h0new = dv*rsqrtf(var + 1e-5f)*gamma0[lane] + beta0[lane];
    g_h0[n*CV+lane] = h0new;
    float nrm  = sqrtf(x*x + y*y + z*z + 1e-12f);
    float mun  = warpsum(nrm) * (1.f/32.f);
    float dn   = nrm - mun;
    float varn = warpsum(dn*dn) * (1.f/32.f);
    float nln  = dn*rsqrtf(varn + 1e-5f)*gamma1[lane];
    float sc   = nln / (nrm + 1e-8f);
    float hx = x*sc, hy = y*sc, hz = z*sc;
    g_h1x[n*CV+lane] = hx;
    g_h1y[n*CV+lane] = hy;
    g_h1z[n*CV+lane] = hz;

    if (do_pre){
        float q=0, p00=0, p10=0;
        float g01x=0,g01y=0,g01z=0,g11x=0,g11y=0,g11z=0;
        #pragma unroll 8
        for (int c = 0; c < CV; c++){
            float hc  = __shfl_sync(0xffffffffu, h0new, c);
            float hcx = __shfl_sync(0xffffffffu, hx, c);
            float hcy = __shfl_sync(0xffffffffu, hy, c);
            float hcz = __shfl_sync(0xffffffffu, hz, c);
            q   += hc*sPq [c*CV+lane];
            p00 += hc*sP00[c*CV+lane];
            p10 += hc*sP10[c*CV+lane];
            float w01 = sP01[c*CV+lane], w11 = sP11[c*CV+lane];
            g01x += hcx*w01; g01y += hcy*w01; g01z += hcz*w01;
            g11x += hcx*w11; g11y += hcy*w11; g11z += hcz*w11;
        }
        g_q  [n*CV+lane] = q;
        g_a00[n*CV+lane] = p00;
        g_a10[n*CV+lane] = p10;
        g_g01x[n*CV+lane]=g01x; g_g01y[n*CV+lane]=g01y; g_g01z[n*CV+lane]=g01z;
        g11wx[n*CV+lane]=g11x; g11wy[n*CV+lane]=g11y; g11wz[n*CV+lane]=g11z;
    }
    if (do_final){
        float wo = Wout[lane];
        float dx = warpsum(hx*wo);
        float dy = warpsum(hy*wo);
        float dz = warpsum(hz*wo);
        if (lane == 0){
            out[n*3+0] = coords[n*3+0] + dx;
            out[n*3+1] = coords[n*3+1] + dy;
            out[n*3+2] = coords[n*3+2] + dz;
        }
    }
}

extern "C" void kernel_launch(void* const* d_in, const int* in_sizes, int n_in,
                              void* d_out, int out_size){
    const float* seq    = (const float*)d_in[0];
    const float* pair   = (const float*)d_in[1];
    const float* bppm   = (const float*)d_in[2];
    const float* coords = (const float*)d_in[3];
    const int*   esrc   = (const int*)  d_in[4];
    const int*   edst   = (const int*)  d_in[5];
    const float* Win0   = (const float*)d_in[6];
    const float* Win1   = (const float*)d_in[7];
    const float* Wr1    = (const float*)d_in[8];
    const float* br1    = (const float*)d_in[9];
    const float* Wr2    = (const float*)d_in[10];
    const float* br2    = (const float*)d_in[11];
    const float* Wm00   = (const float*)d_in[12];
    const float* Wm01   = (const float*)d_in[13];
    const float* Wm10   = (const float*)d_in[14];
    const float* Wm11   = (const float*)d_in[15];
    const float* Wq     = (const float*)d_in[16];
    const float* Wself0 = (const float*)d_in[17];
    const float* Wself1 = (const float*)d_in[18];
    const float* gamma0 = (const float*)d_in[19];
    const float* beta0  = (const float*)d_in[20];
    const float* gamma1 = (const float*)d_in[21];
    const float* Wout   = (const float*)d_in[22];

    int E = in_sizes[4];
    if (E > EMAX) E = EMAX;

    static cudaStream_t s2 = nullptr;
    static cudaEvent_t evRoot = nullptr, evSetup = nullptr, evBtab = nullptr;
    static cudaEvent_t evM[NLV] = {nullptr, nullptr, nullptr};
    if (s2 == nullptr){
        cudaStreamCreateWithFlags(&s2, cudaStreamNonBlocking);
        cudaEventCreateWithFlags(&evRoot,  cudaEventDisableTiming);
        cudaEventCreateWithFlags(&evSetup, cudaEventDisableTiming);
        cudaEventCreateWithFlags(&evBtab,  cudaEventDisableTiming);
        for (int l = 0; l < NLV; l++)
            cudaEventCreateWithFlags(&evM[l], cudaEventDisableTiming);
        cudaFuncSetAttribute(k_mma_rad,
            cudaFuncAttributeMaxDynamicSharedMemorySize, SM_BYTES);
        cudaFuncSetAttribute(k_init_nodes,
            cudaFuncAttributeMaxDynamicSharedMemorySize, (20480+16*D0V)*4);
    }

    // side stream: edge setup first
    cudaEventRecord(evRoot, 0);
    cudaStreamWaitEvent(s2, evRoot, 0);
    k_edge_setup<<<1480, 256, 0, s2>>>(coords, pair, bppm, esrc, edst, E);

    // main head: B tables first so the MMA chain can start right after setup
    k_btab<<<24, 256>>>(Wr1, Wr2);
    cudaEventRecord(evBtab, 0);

    // side stream: all 3 layers' radial GEMMs (need setup [in-order on s2] + btab)
    cudaStreamWaitEvent(s2, evBtab, 0);
    for (int l = 0; l < NLV; l++){
        k_mma_rad<<<296, 128, SM_BYTES, s2>>>(Wr1 + l*RADIN*HIDV,
            br1 + l*HIDV, br2 + l*R4C, E, l);
        cudaEventRecord(evM[l], s2);
    }
    cudaEventRecord(evSetup, s2);   // marks setup done (and more) — only used below scan

    // main stream head
    k_init_nodes<<<128, 512, (20480+16*D0V)*4>>>(seq, coords, Win0, Win1);
    k_node_pre<<<128, 256>>>(Wq, Wm00, Wm10, Wm01, Wm11);

    // CSR build on main (needs edge_setup's g_deg -> gate on first MMA event,
    // which transitively implies setup completed on s2's in-order stream)
    cudaStreamWaitEvent(0, evM[0], 0);
    k_scan<<<1, 1024>>>(E);
    k_fill<<<(E+255)/256, 256>>>(edst, E);

    for (int l = 0; l < NLV; l++){
        int lp = l + 1;
        int rb = l & 1;
        int do_pre = (l < NLV-1);
        int do_fin = (l == NLV-1);
        cudaStreamWaitEvent(0, evM[l], 0);
        k_tail<<<(E+127)/128, 256>>>(esrc, edst, E, l);
        k_node_agg<<<512, 256>>>(esrc,
            Wself0 + l*CV*CV, Wself1 + l*CV*CV,
            gamma0 + l*CV, beta0 + l*CV, gamma1 + l*CV,
            Wq + (do_pre ? lp*CV*CV : 0), Wm00 + (do_pre ? lp*CV*CV : 0),
            Wm10 + (do_pre ? lp*CV*CV : 0), Wm01 + (do_pre ? lp*CV*CV : 0),
            Wm11 + (do_pre ? lp*CV*CV : 0), do_pre,
            Wout, coords, (float*)d_out, do_fin, rb);
    }
}